// round 15
// baseline (speedup 1.0000x reference)
#include <cuda_runtime.h>
#include <cuda_fp16.h>
#include <math.h>
#include <stdint.h>

// Problem constants
#define B_    2
#define N_    2048
#define DM    1024
#define H_    16
#define HD    64
#define MTOT  (B_ * N_)   // 4096

// fp16 scratch (allocation-free rule: __device__ globals)
__device__ __align__(16) __half g_Xh[MTOT * DM];
__device__ __align__(16) __half g_Wqh[DM * DM];
__device__ __align__(16) __half g_Wkh[DM * DM];
__device__ __align__(16) __half g_Wvh[DM * DM];
__device__ __align__(16) __half g_Woh[DM * DM];
__device__ __align__(16) __half g_Qh[MTOT * DM];
__device__ __align__(16) __half g_Kh[MTOT * DM];
__device__ __align__(16) __half g_Vh[MTOT * DM];
__device__ __align__(16) __half g_Ch[MTOT * DM];

// ---------------------------------------------------------------------------
// Helpers
// ---------------------------------------------------------------------------
__device__ __forceinline__ void cp16(void* smem_ptr, const void* gmem_ptr) {
    uint32_t s = (uint32_t)__cvta_generic_to_shared(smem_ptr);
    asm volatile("cp.async.cg.shared.global [%0], [%1], 16;" :: "r"(s), "l"(gmem_ptr));
}
__device__ __forceinline__ void cp_commit() { asm volatile("cp.async.commit_group;"); }
__device__ __forceinline__ void cp_wait0()  { asm volatile("cp.async.wait_group 0;"); }

__device__ __forceinline__ uint32_t ex2_h2(uint32_t x) {
    uint32_t y;
    asm("ex2.approx.f16x2 %0, %1;" : "=r"(y) : "r"(x));
    return y;
}

__device__ __forceinline__ void ldsm_x4(uint32_t* r, const void* p) {
    uint32_t a = (uint32_t)__cvta_generic_to_shared(p);
    asm volatile("ldmatrix.sync.aligned.m8n8.x4.shared.b16 {%0,%1,%2,%3}, [%4];"
                 : "=r"(r[0]), "=r"(r[1]), "=r"(r[2]), "=r"(r[3]) : "r"(a));
}
__device__ __forceinline__ void ldsm_x4_t(uint32_t* r, const void* p) {
    uint32_t a = (uint32_t)__cvta_generic_to_shared(p);
    asm volatile("ldmatrix.sync.aligned.m8n8.x4.trans.shared.b16 {%0,%1,%2,%3}, [%4];"
                 : "=r"(r[0]), "=r"(r[1]), "=r"(r[2]), "=r"(r[3]) : "r"(a));
}

__device__ __forceinline__ void mma_f16(float* d, const uint32_t* a, const uint32_t* b) {
    asm volatile(
        "mma.sync.aligned.m16n8k16.row.col.f32.f16.f16.f32 "
        "{%0,%1,%2,%3}, {%4,%5,%6,%7}, {%8,%9}, {%0,%1,%2,%3};\n"
        : "+f"(d[0]), "+f"(d[1]), "+f"(d[2]), "+f"(d[3])
        : "r"(a[0]), "r"(a[1]), "r"(a[2]), "r"(a[3]), "r"(b[0]), "r"(b[1]));
}

// ---------------------------------------------------------------------------
// fp32 -> fp16 cast kernel
// ---------------------------------------------------------------------------
__global__ void cast_half(const float4* __restrict__ src, uint2* __restrict__ dst, int n4)
{
    int i = blockIdx.x * blockDim.x + threadIdx.x;
    if (i < n4) {
        float4 v = src[i];
        __half2 lo = __floats2half2_rn(v.x, v.y);
        __half2 hi = __floats2half2_rn(v.z, v.w);
        uint2 o;
        o.x = *(uint32_t*)&lo;
        o.y = *(uint32_t*)&hi;
        dst[i] = o;
    }
}

// ---------------------------------------------------------------------------
// fp16 tensor-core GEMM (2-stage, proven): C = alpha*A[M,K]@B[K,N]
// 128x128 block tile, BK=64, 256 threads (8 warps), warp tile 64x32.
// blockIdx.z selects (B, C, alpha); by0 offsets the M-tile (batch split).
// ---------------------------------------------------------------------------
struct GArgs {
    const __half* B[3];
    void* C[3];
    float alpha[3];
};

#define GBK 64

template<bool HOUT>
__global__ void __launch_bounds__(256, 2)
gemm_f16(const __half* __restrict__ A, GArgs args, int M, int N, int K, int by0)
{
    extern __shared__ __half smh[];
    __half* As = smh;                     // [2][128][64]
    __half* Bs = smh + 2 * 128 * 64;      // [2][64][128]

    const __half* Bm = args.B[blockIdx.z];
    void* Cv = args.C[blockIdx.z];
    const float alpha = args.alpha[blockIdx.z];

    const int tid = threadIdx.x;
    const int bx = blockIdx.x, by = blockIdx.y + by0;
    const int wid = tid >> 5, lid = tid & 31;
    const int wm = wid & 1;
    const int wn = wid >> 1;
    const int gid = lid >> 2, tig = lid & 3;
    const int q = lid >> 3, rr = lid & 7;

    float acc[4][4][4];
#pragma unroll
    for (int mt = 0; mt < 4; mt++)
#pragma unroll
        for (int nt = 0; nt < 4; nt++)
#pragma unroll
            for (int c = 0; c < 4; c++) acc[mt][nt][c] = 0.0f;

    auto load_stage = [&](int s, int k0) {
        __half* Asb = As + s * 128 * 64;
        __half* Bsb = Bs + s * 64 * 128;
#pragma unroll
        for (int j = 0; j < 4; j++) {
            int i = tid + 256 * j;
            int row = i >> 3, ch = i & 7;
            cp16(&Asb[row * 64 + ((ch ^ (row & 7)) << 3)],
                 A + (size_t)(by * 128 + row) * K + k0 + ch * 8);
            int rowb = i >> 4, chb = i & 15;
            cp16(&Bsb[rowb * 128 + ((chb ^ (rowb & 7)) << 3)],
                 Bm + (size_t)(k0 + rowb) * N + bx * 128 + chb * 8);
        }
        cp_commit();
    };

    load_stage(0, 0);
    const int S = K / GBK;

    for (int it = 0; it < S; it++) {
        cp_wait0();
        __syncthreads();
        if (it + 1 < S) load_stage((it + 1) & 1, (it + 1) * GBK);

        const __half* Asb = As + (it & 1) * 128 * 64;
        const __half* Bsb = Bs + (it & 1) * 64 * 128;

#pragma unroll
        for (int kt = 0; kt < 4; kt++) {
            uint32_t afr[4][4], bfr[4][2];
#pragma unroll
            for (int mt = 0; mt < 4; mt++) {
                int row = wm * 64 + mt * 16 + (q & 1) * 8 + rr;
                int kch = kt * 2 + (q >> 1);
                ldsm_x4(afr[mt], &Asb[row * 64 + ((kch ^ (row & 7)) << 3)]);
            }
#pragma unroll
            for (int p = 0; p < 2; p++) {
                uint32_t t4[4];
                int krow = kt * 16 + (q & 1) * 8 + rr;
                int nch = wn * 4 + p * 2 + (q >> 1);
                ldsm_x4_t(t4, &Bsb[krow * 128 + ((nch ^ (krow & 7)) << 3)]);
                bfr[2 * p][0] = t4[0]; bfr[2 * p][1] = t4[1];
                bfr[2 * p + 1][0] = t4[2]; bfr[2 * p + 1][1] = t4[3];
            }
#pragma unroll
            for (int mt = 0; mt < 4; mt++)
#pragma unroll
                for (int nt = 0; nt < 4; nt++)
                    mma_f16(acc[mt][nt], afr[mt], bfr[nt]);
        }
        __syncthreads();
    }

#pragma unroll
    for (int mt = 0; mt < 4; mt++) {
#pragma unroll
        for (int nt = 0; nt < 4; nt++) {
            int row0 = by * 128 + wm * 64 + mt * 16 + gid;
            int col = bx * 128 + wn * 32 + nt * 8 + tig * 2;
            if (HOUT) {
                __half* C = (__half*)Cv;
                __half2 v0 = __floats2half2_rn(acc[mt][nt][0] * alpha, acc[mt][nt][1] * alpha);
                __half2 v1 = __floats2half2_rn(acc[mt][nt][2] * alpha, acc[mt][nt][3] * alpha);
                *(__half2*)&C[(size_t)row0 * N + col] = v0;
                *(__half2*)&C[(size_t)(row0 + 8) * N + col] = v1;
            } else {
                float* C = (float*)Cv;
                *(float2*)&C[(size_t)row0 * N + col] =
                    make_float2(acc[mt][nt][0] * alpha, acc[mt][nt][1] * alpha);
                *(float2*)&C[(size_t)(row0 + 8) * N + col] =
                    make_float2(acc[mt][nt][2] * alpha, acc[mt][nt][3] * alpha);
            }
        }
    }
}

// ---------------------------------------------------------------------------
// fp16 tensor-core causal flash attention, static-max softmax (ones-mma row
// sums) + warp early-out on fully-masked diagonal tiles (p==0 contribution).
// b0 selects the batch (batch split across streams).
// ---------------------------------------------------------------------------
#define NEG_BIG (-1e30f)
#define SM_SHIFT 4.0f

__global__ void __launch_bounds__(128, 2)
attn_f16(const __half* __restrict__ Q, const __half* __restrict__ K,
         const __half* __restrict__ V, __half* __restrict__ Ctx, int b0)
{
    __shared__ __align__(16) __half Ks[2][64 * 64];
    __shared__ __align__(16) __half Vs[2][64 * 64];

    const int qt = (gridDim.x - 1) - blockIdx.x;
    const int h  = blockIdx.y;
    const int b  = b0;
    const int tid = threadIdx.x;
    const int w = tid >> 5, lid = tid & 31;
    const int gid = lid >> 2, tig = lid & 3;
    const int q = lid >> 3, rr = lid & 7;

    const int rowbase = qt * 128 + w * 32;
    int rq[2][2];
    rq[0][0] = rowbase + gid;      rq[0][1] = rowbase + 8 + gid;
    rq[1][0] = rowbase + 16 + gid; rq[1][1] = rowbase + 24 + gid;

    uint32_t qf[2][4][4];
#pragma unroll
    for (int sl = 0; sl < 2; sl++) {
        const __half* q0 = Q + ((size_t)(b * N_ + rq[sl][0])) * DM + h * HD;
        const __half* q1 = Q + ((size_t)(b * N_ + rq[sl][1])) * DM + h * HD;
#pragma unroll
        for (int kt = 0; kt < 4; kt++) {
            int c = kt * 16 + 2 * tig;
            qf[sl][kt][0] = *(const uint32_t*)(q0 + c);
            qf[sl][kt][1] = *(const uint32_t*)(q1 + c);
            qf[sl][kt][2] = *(const uint32_t*)(q0 + c + 8);
            qf[sl][kt][3] = *(const uint32_t*)(q1 + c + 8);
        }
    }

    float o[2][8][4];
#pragma unroll
    for (int sl = 0; sl < 2; sl++)
#pragma unroll
        for (int nt = 0; nt < 8; nt++)
#pragma unroll
            for (int c = 0; c < 4; c++) o[sl][nt][c] = 0.0f;
    float lf[2][4];
#pragma unroll
    for (int sl = 0; sl < 2; sl++)
#pragma unroll
        for (int c = 0; c < 4; c++) lf[sl][c] = 0.0f;

    const __half2 shift2 = __floats2half2_rn(SM_SHIFT, SM_SHIFT);
    const uint32_t ones = 0x3C003C00u;            // half2(1,1)
    const uint32_t ones_b[2] = {ones, ones};

    const int nIters = 2 * (qt + 1);

    auto load_tile = [&](int t, int st) {
        const __half* kb = K + ((size_t)(b * N_ + t * 64)) * DM + h * HD;
        const __half* vb = V + ((size_t)(b * N_ + t * 64)) * DM + h * HD;
#pragma unroll
        for (int j = 0; j < 8; j++) {
            int i = tid + 128 * j;
            int rem = i & 511;
            int row = rem >> 3, ch = rem & 7;
            int soff = row * 64 + ((ch ^ (row & 7)) << 3);
            if (i < 512) cp16(&Ks[st][soff], kb + (size_t)row * DM + ch * 8);
            else         cp16(&Vs[st][soff], vb + (size_t)row * DM + ch * 8);
        }
        cp_commit();
    };

    load_tile(0, 0);

    for (int t = 0; t < nIters; t++) {
        cp_wait0();
        __syncthreads();
        if (t + 1 < nIters) load_tile(t + 1, (t + 1) & 1);

        // warp early-out: all keys of this tile lie above all my query rows
        // -> p == 0 for every element; O and l unchanged. Loads/syncs ran.
        if (t * 64 > rowbase + 31) continue;

        const __half* Kb = Ks[t & 1];
        const __half* Vb = Vs[t & 1];

        // ---- S = Q K^T ----
        float s[2][8][4];
#pragma unroll
        for (int sl = 0; sl < 2; sl++)
#pragma unroll
            for (int nt = 0; nt < 8; nt++)
#pragma unroll
                for (int c = 0; c < 4; c++) s[sl][nt][c] = 0.0f;

#pragma unroll
        for (int kt = 0; kt < 4; kt++) {
#pragma unroll
            for (int p = 0; p < 4; p++) {
                uint32_t t4[4];
                int krow = p * 16 + (q >> 1) * 8 + rr;
                int dch = kt * 2 + (q & 1);
                ldsm_x4(t4, &Kb[krow * 64 + ((dch ^ (krow & 7)) << 3)]);
                uint32_t b0v[2] = {t4[0], t4[1]};
                uint32_t b1v[2] = {t4[2], t4[3]};
                mma_f16(s[0][2 * p],     qf[0][kt], b0v);
                mma_f16(s[0][2 * p + 1], qf[0][kt], b1v);
                mma_f16(s[1][2 * p],     qf[1][kt], b0v);
                mma_f16(s[1][2 * p + 1], qf[1][kt], b1v);
            }
        }

        // ---- causal mask (diagonal-overlap tiles only) ----
        if ((t * 64 + 63) > rowbase) {
#pragma unroll
            for (int sl = 0; sl < 2; sl++)
#pragma unroll
                for (int nt = 0; nt < 8; nt++) {
                    int key = t * 64 + nt * 8 + 2 * tig;
                    if (key > rq[sl][0])     s[sl][nt][0] = NEG_BIG;
                    if (key + 1 > rq[sl][0]) s[sl][nt][1] = NEG_BIG;
                    if (key > rq[sl][1])     s[sl][nt][2] = NEG_BIG;
                    if (key + 1 > rq[sl][1]) s[sl][nt][3] = NEG_BIG;
                }
        }

        // ---- P = exp2(S - 4); O += P V; l += P @ ones ----
#pragma unroll
        for (int kt = 0; kt < 4; kt++) {
            uint32_t pa[2][4];
#pragma unroll
            for (int sl = 0; sl < 2; sl++) {
                __half2 h0v = __hsub2(__floats2half2_rn(s[sl][2 * kt][0],     s[sl][2 * kt][1]),     shift2);
                __half2 h1v = __hsub2(__floats2half2_rn(s[sl][2 * kt][2],     s[sl][2 * kt][3]),     shift2);
                __half2 h2v = __hsub2(__floats2half2_rn(s[sl][2 * kt + 1][0], s[sl][2 * kt + 1][1]), shift2);
                __half2 h3v = __hsub2(__floats2half2_rn(s[sl][2 * kt + 1][2], s[sl][2 * kt + 1][3]), shift2);
                pa[sl][0] = ex2_h2(*(uint32_t*)&h0v);
                pa[sl][1] = ex2_h2(*(uint32_t*)&h1v);
                pa[sl][2] = ex2_h2(*(uint32_t*)&h2v);
                pa[sl][3] = ex2_h2(*(uint32_t*)&h3v);
            }
            mma_f16(lf[0], pa[0], ones_b);
            mma_f16(lf[1], pa[1], ones_b);
#pragma unroll
            for (int p = 0; p < 4; p++) {
                uint32_t t4[4];
                int krow = kt * 16 + (q & 1) * 8 + rr;
                int dch = 2 * p + (q >> 1);
                ldsm_x4_t(t4, &Vb[krow * 64 + ((dch ^ (krow & 7)) << 3)]);
                uint32_t b0v[2] = {t4[0], t4[1]};
                uint32_t b1v[2] = {t4[2], t4[3]};
                mma_f16(o[0][2 * p],     pa[0], b0v);
                mma_f16(o[0][2 * p + 1], pa[0], b1v);
                mma_f16(o[1][2 * p],     pa[1], b0v);
                mma_f16(o[1][2 * p + 1], pa[1], b1v);
            }
        }
    }

    // ---- epilogue: normalize by l, store fp16 ----
#pragma unroll
    for (int sl = 0; sl < 2; sl++) {
        float inv0 = 1.0f / lf[sl][0], inv1 = 1.0f / lf[sl][2];
        __half* c0 = Ctx + ((size_t)(b * N_ + rq[sl][0])) * DM + h * HD;
        __half* c1 = Ctx + ((size_t)(b * N_ + rq[sl][1])) * DM + h * HD;
#pragma unroll
        for (int nt = 0; nt < 8; nt++) {
            int col = nt * 8 + 2 * tig;
            __half2 v0 = __floats2half2_rn(o[sl][nt][0] * inv0, o[sl][nt][1] * inv0);
            __half2 v1 = __floats2half2_rn(o[sl][nt][2] * inv1, o[sl][nt][3] * inv1);
            *(__half2*)(c0 + col) = v0;
            *(__half2*)(c1 + col) = v1;
        }
    }
}

// ---------------------------------------------------------------------------
// Launch: batch-split two-stream pipeline; parallel cast prefix folded into
// the SAME two side streams (no extra streams -> no upload alloc).
// ---------------------------------------------------------------------------
#define GEMM_SMEM (2 * (128 * 64 + 64 * 128) * (int)sizeof(__half))  // 64 KB

extern "C" void kernel_launch(void* const* d_in, const int* in_sizes, int n_in,
                              void* d_out, int out_size)
{
    const float* x  = (const float*)d_in[0];
    const float* Wq = (const float*)d_in[1];
    const float* Wk = (const float*)d_in[2];
    const float* Wv = (const float*)d_in[3];
    const float* Wo = (const float*)d_in[4];
    float* out = (float*)d_out;

    __half *Xh, *Wqh, *Wkh, *Wvh, *Woh, *Qh, *Kh, *Vh, *Ch;
    cudaGetSymbolAddress((void**)&Xh, g_Xh);
    cudaGetSymbolAddress((void**)&Wqh, g_Wqh);
    cudaGetSymbolAddress((void**)&Wkh, g_Wkh);
    cudaGetSymbolAddress((void**)&Wvh, g_Wvh);
    cudaGetSymbolAddress((void**)&Woh, g_Woh);
    cudaGetSymbolAddress((void**)&Qh, g_Qh);
    cudaGetSymbolAddress((void**)&Kh, g_Kh);
    cudaGetSymbolAddress((void**)&Vh, g_Vh);
    cudaGetSymbolAddress((void**)&Ch, g_Ch);

    static cudaStream_t s2 = nullptr, s3 = nullptr;
    static cudaEvent_t evRoot = nullptr, evWqk = nullptr, evWv = nullptr;
    static cudaEvent_t evWo = nullptr, evJ = nullptr;
    static bool init_done = false;
    if (!init_done) {
        cudaFuncSetAttribute(gemm_f16<true>,  cudaFuncAttributeMaxDynamicSharedMemorySize, GEMM_SMEM);
        cudaFuncSetAttribute(gemm_f16<false>, cudaFuncAttributeMaxDynamicSharedMemorySize, GEMM_SMEM);
        cudaStreamCreateWithFlags(&s2, cudaStreamNonBlocking);
        cudaStreamCreateWithFlags(&s3, cudaStreamNonBlocking);
        cudaEventCreateWithFlags(&evRoot, cudaEventDisableTiming);
        cudaEventCreateWithFlags(&evWqk, cudaEventDisableTiming);
        cudaEventCreateWithFlags(&evWv, cudaEventDisableTiming);
        cudaEventCreateWithFlags(&evWo, cudaEventDisableTiming);
        cudaEventCreateWithFlags(&evJ, cudaEventDisableTiming);
        init_done = true;
    }

    const int n4x = MTOT * DM / 4, n4w = DM * DM / 4;
    const int n4xh = n4x / 2;   // x half (one batch)

    // ---- capture-legal fork of the two side streams from the origin ----
    cudaEventRecord(evRoot, 0);
    cudaStreamWaitEvent(s2, evRoot, 0);
    cudaStreamWaitEvent(s3, evRoot, 0);

    // ---- parallel cast prefix (2 side streams only) ----
    cast_half<<<(n4w + 255) / 256, 256, 0, s3>>>((const float4*)Wq, (uint2*)Wqh, n4w);
    cast_half<<<(n4w + 255) / 256, 256, 0, s3>>>((const float4*)Wk, (uint2*)Wkh, n4w);
    cudaEventRecord(evWqk, s3);
    cast_half<<<(n4w + 255) / 256, 256, 0, s3>>>((const float4*)Wo, (uint2*)Woh, n4w);
    cudaEventRecord(evWo, s3);
    cast_half<<<(n4w + 255) / 256, 256, 0, s2>>>((const float4*)Wv, (uint2*)Wvh, n4w);
    cudaEventRecord(evWv, s2);
    cast_half<<<(n4xh + 255) / 256, 256, 0, s2>>>((const float4*)x + n4xh,
                                                  (uint2*)Xh + n4xh, n4xh);
    cast_half<<<(n4xh + 255) / 256, 256>>>((const float4*)x, (uint2*)Xh, n4xh);

    cudaStreamWaitEvent(0, evWqk, 0);
    cudaStreamWaitEvent(0, evWv, 0);
    cudaStreamWaitEvent(s2, evWqk, 0);

    const float qalpha = 0.125f * 1.4426950408889634f;
    GArgs qkv;
    qkv.B[0] = Wqh; qkv.B[1] = Wkh; qkv.B[2] = Wvh;
    qkv.C[0] = Qh;  qkv.C[1] = Kh;  qkv.C[2] = Vh;
    qkv.alpha[0] = qalpha; qkv.alpha[1] = 1.0f; qkv.alpha[2] = 1.0f;

    GArgs og;
    og.B[0] = Woh; og.C[0] = out; og.alpha[0] = 1.0f;
    og.B[1] = Woh; og.C[1] = out; og.alpha[1] = 1.0f;
    og.B[2] = Woh; og.C[2] = out; og.alpha[2] = 1.0f;

    // ---- stream 0: full chain for batch 0 (M-tiles 0..15) ----
    gemm_f16<true><<<dim3(8, 16, 3), 256, GEMM_SMEM>>>(Xh, qkv, MTOT, DM, DM, 0);
    attn_f16<<<dim3(N_ / 128, H_, 1), 128>>>(Qh, Kh, Vh, Ch, 0);
    cudaStreamWaitEvent(0, evWo, 0);
    gemm_f16<false><<<dim3(8, 16, 1), 256, GEMM_SMEM>>>(Ch, og, MTOT, DM, DM, 0);

    // ---- stream s2: full chain for batch 1 (M-tiles 16..31) ----
    gemm_f16<true><<<dim3(8, 16, 3), 256, GEMM_SMEM, s2>>>(Xh, qkv, MTOT, DM, DM, 16);
    attn_f16<<<dim3(N_ / 128, H_, 1), 128, 0, s2>>>(Qh, Kh, Vh, Ch, 1);
    cudaStreamWaitEvent(s2, evWo, 0);
    gemm_f16<false><<<dim3(8, 16, 1), 256, GEMM_SMEM, s2>>>(Ch, og, MTOT, DM, DM, 16);

    // ---- join: origin stream waits for s2's chain ----
    cudaEventRecord(evJ, s2);
    cudaStreamWaitEvent(0, evJ, 0);
}

// round 16
// speedup vs baseline: 1.0285x; 1.0285x over previous
#include <cuda_runtime.h>
#include <cuda_fp16.h>
#include <math.h>
#include <stdint.h>

// Problem constants
#define B_    2
#define N_    2048
#define DM    1024
#define H_    16
#define HD    64
#define MTOT  (B_ * N_)   // 4096

// fp16 scratch (allocation-free rule: __device__ globals)
__device__ __align__(16) __half g_Xh[MTOT * DM];
__device__ __align__(16) __half g_Wqh[DM * DM];
__device__ __align__(16) __half g_Wkh[DM * DM];
__device__ __align__(16) __half g_Wvh[DM * DM];
__device__ __align__(16) __half g_Woh[DM * DM];
__device__ __align__(16) __half g_Qh[MTOT * DM];
__device__ __align__(16) __half g_Kh[MTOT * DM];
__device__ __align__(16) __half g_Vh[MTOT * DM];
__device__ __align__(16) __half g_Ch[MTOT * DM];

// ---------------------------------------------------------------------------
// Helpers
// ---------------------------------------------------------------------------
__device__ __forceinline__ void cp16(void* smem_ptr, const void* gmem_ptr) {
    uint32_t s = (uint32_t)__cvta_generic_to_shared(smem_ptr);
    asm volatile("cp.async.cg.shared.global [%0], [%1], 16;" :: "r"(s), "l"(gmem_ptr));
}
__device__ __forceinline__ void cp_commit() { asm volatile("cp.async.commit_group;"); }
__device__ __forceinline__ void cp_wait0()  { asm volatile("cp.async.wait_group 0;"); }

__device__ __forceinline__ uint32_t ex2_h2(uint32_t x) {
    uint32_t y;
    asm("ex2.approx.f16x2 %0, %1;" : "=r"(y) : "r"(x));
    return y;
}

__device__ __forceinline__ void ldsm_x4(uint32_t* r, const void* p) {
    uint32_t a = (uint32_t)__cvta_generic_to_shared(p);
    asm volatile("ldmatrix.sync.aligned.m8n8.x4.shared.b16 {%0,%1,%2,%3}, [%4];"
                 : "=r"(r[0]), "=r"(r[1]), "=r"(r[2]), "=r"(r[3]) : "r"(a));
}
__device__ __forceinline__ void ldsm_x4_t(uint32_t* r, const void* p) {
    uint32_t a = (uint32_t)__cvta_generic_to_shared(p);
    asm volatile("ldmatrix.sync.aligned.m8n8.x4.trans.shared.b16 {%0,%1,%2,%3}, [%4];"
                 : "=r"(r[0]), "=r"(r[1]), "=r"(r[2]), "=r"(r[3]) : "r"(a));
}

__device__ __forceinline__ void mma_f16(float* d, const uint32_t* a, const uint32_t* b) {
    asm volatile(
        "mma.sync.aligned.m16n8k16.row.col.f32.f16.f16.f32 "
        "{%0,%1,%2,%3}, {%4,%5,%6,%7}, {%8,%9}, {%0,%1,%2,%3};\n"
        : "+f"(d[0]), "+f"(d[1]), "+f"(d[2]), "+f"(d[3])
        : "r"(a[0]), "r"(a[1]), "r"(a[2]), "r"(a[3]), "r"(b[0]), "r"(b[1]));
}

__device__ __forceinline__ uint32_t hadd2u(uint32_t a, uint32_t b) {
    __half2 r = __hadd2(*(__half2*)&a, *(__half2*)&b);
    return *(uint32_t*)&r;
}

// ---------------------------------------------------------------------------
// fp32 -> fp16 cast kernel
// ---------------------------------------------------------------------------
__global__ void cast_half(const float4* __restrict__ src, uint2* __restrict__ dst, int n4)
{
    int i = blockIdx.x * blockDim.x + threadIdx.x;
    if (i < n4) {
        float4 v = src[i];
        __half2 lo = __floats2half2_rn(v.x, v.y);
        __half2 hi = __floats2half2_rn(v.z, v.w);
        uint2 o;
        o.x = *(uint32_t*)&lo;
        o.y = *(uint32_t*)&hi;
        dst[i] = o;
    }
}

// ---------------------------------------------------------------------------
// fp16 tensor-core GEMM (2-stage, proven): C = alpha*A[M,K]@B[K,N]
// 128x128 block tile, BK=64, 256 threads (8 warps), warp tile 64x32.
// blockIdx.z selects (B, C, alpha); by0 offsets the M-tile (batch split).
// ---------------------------------------------------------------------------
struct GArgs {
    const __half* B[3];
    void* C[3];
    float alpha[3];
};

#define GBK 64

template<bool HOUT>
__global__ void __launch_bounds__(256, 2)
gemm_f16(const __half* __restrict__ A, GArgs args, int M, int N, int K, int by0)
{
    extern __shared__ __half smh[];
    __half* As = smh;                     // [2][128][64]
    __half* Bs = smh + 2 * 128 * 64;      // [2][64][128]

    const __half* Bm = args.B[blockIdx.z];
    void* Cv = args.C[blockIdx.z];
    const float alpha = args.alpha[blockIdx.z];

    const int tid = threadIdx.x;
    const int bx = blockIdx.x, by = blockIdx.y + by0;
    const int wid = tid >> 5, lid = tid & 31;
    const int wm = wid & 1;
    const int wn = wid >> 1;
    const int gid = lid >> 2, tig = lid & 3;
    const int q = lid >> 3, rr = lid & 7;

    float acc[4][4][4];
#pragma unroll
    for (int mt = 0; mt < 4; mt++)
#pragma unroll
        for (int nt = 0; nt < 4; nt++)
#pragma unroll
            for (int c = 0; c < 4; c++) acc[mt][nt][c] = 0.0f;

    auto load_stage = [&](int s, int k0) {
        __half* Asb = As + s * 128 * 64;
        __half* Bsb = Bs + s * 64 * 128;
#pragma unroll
        for (int j = 0; j < 4; j++) {
            int i = tid + 256 * j;
            int row = i >> 3, ch = i & 7;
            cp16(&Asb[row * 64 + ((ch ^ (row & 7)) << 3)],
                 A + (size_t)(by * 128 + row) * K + k0 + ch * 8);
            int rowb = i >> 4, chb = i & 15;
            cp16(&Bsb[rowb * 128 + ((chb ^ (rowb & 7)) << 3)],
                 Bm + (size_t)(k0 + rowb) * N + bx * 128 + chb * 8);
        }
        cp_commit();
    };

    load_stage(0, 0);
    const int S = K / GBK;

    for (int it = 0; it < S; it++) {
        cp_wait0();
        __syncthreads();
        if (it + 1 < S) load_stage((it + 1) & 1, (it + 1) * GBK);

        const __half* Asb = As + (it & 1) * 128 * 64;
        const __half* Bsb = Bs + (it & 1) * 64 * 128;

#pragma unroll
        for (int kt = 0; kt < 4; kt++) {
            uint32_t afr[4][4], bfr[4][2];
#pragma unroll
            for (int mt = 0; mt < 4; mt++) {
                int row = wm * 64 + mt * 16 + (q & 1) * 8 + rr;
                int kch = kt * 2 + (q >> 1);
                ldsm_x4(afr[mt], &Asb[row * 64 + ((kch ^ (row & 7)) << 3)]);
            }
#pragma unroll
            for (int p = 0; p < 2; p++) {
                uint32_t t4[4];
                int krow = kt * 16 + (q & 1) * 8 + rr;
                int nch = wn * 4 + p * 2 + (q >> 1);
                ldsm_x4_t(t4, &Bsb[krow * 128 + ((nch ^ (krow & 7)) << 3)]);
                bfr[2 * p][0] = t4[0]; bfr[2 * p][1] = t4[1];
                bfr[2 * p + 1][0] = t4[2]; bfr[2 * p + 1][1] = t4[3];
            }
#pragma unroll
            for (int mt = 0; mt < 4; mt++)
#pragma unroll
                for (int nt = 0; nt < 4; nt++)
                    mma_f16(acc[mt][nt], afr[mt], bfr[nt]);
        }
        __syncthreads();
    }

#pragma unroll
    for (int mt = 0; mt < 4; mt++) {
#pragma unroll
        for (int nt = 0; nt < 4; nt++) {
            int row0 = by * 128 + wm * 64 + mt * 16 + gid;
            int col = bx * 128 + wn * 32 + nt * 8 + tig * 2;
            if (HOUT) {
                __half* C = (__half*)Cv;
                __half2 v0 = __floats2half2_rn(acc[mt][nt][0] * alpha, acc[mt][nt][1] * alpha);
                __half2 v1 = __floats2half2_rn(acc[mt][nt][2] * alpha, acc[mt][nt][3] * alpha);
                *(__half2*)&C[(size_t)row0 * N + col] = v0;
                *(__half2*)&C[(size_t)(row0 + 8) * N + col] = v1;
            } else {
                float* C = (float*)Cv;
                *(float2*)&C[(size_t)row0 * N + col] =
                    make_float2(acc[mt][nt][0] * alpha, acc[mt][nt][1] * alpha);
                *(float2*)&C[(size_t)(row0 + 8) * N + col] =
                    make_float2(acc[mt][nt][2] * alpha, acc[mt][nt][3] * alpha);
            }
        }
    }
}

// ---------------------------------------------------------------------------
// fp16 tensor-core causal flash attention, static-max softmax.
// Row sums via ONE deferred ones-mma per slab per tile: P fragments summed
// over kt in f16 (linearity of mma in A), then a single fp32 mma.
// b0 selects the batch (batch split across streams).
// ---------------------------------------------------------------------------
#define NEG_BIG (-1e30f)
#define SM_SHIFT 4.0f

__global__ void __launch_bounds__(128, 2)
attn_f16(const __half* __restrict__ Q, const __half* __restrict__ K,
         const __half* __restrict__ V, __half* __restrict__ Ctx, int b0)
{
    __shared__ __align__(16) __half Ks[2][64 * 64];
    __shared__ __align__(16) __half Vs[2][64 * 64];

    const int qt = (gridDim.x - 1) - blockIdx.x;
    const int h  = blockIdx.y;
    const int b  = b0;
    const int tid = threadIdx.x;
    const int w = tid >> 5, lid = tid & 31;
    const int gid = lid >> 2, tig = lid & 3;
    const int q = lid >> 3, rr = lid & 7;

    const int rowbase = qt * 128 + w * 32;
    int rq[2][2];
    rq[0][0] = rowbase + gid;      rq[0][1] = rowbase + 8 + gid;
    rq[1][0] = rowbase + 16 + gid; rq[1][1] = rowbase + 24 + gid;

    uint32_t qf[2][4][4];
#pragma unroll
    for (int sl = 0; sl < 2; sl++) {
        const __half* q0 = Q + ((size_t)(b * N_ + rq[sl][0])) * DM + h * HD;
        const __half* q1 = Q + ((size_t)(b * N_ + rq[sl][1])) * DM + h * HD;
#pragma unroll
        for (int kt = 0; kt < 4; kt++) {
            int c = kt * 16 + 2 * tig;
            qf[sl][kt][0] = *(const uint32_t*)(q0 + c);
            qf[sl][kt][1] = *(const uint32_t*)(q1 + c);
            qf[sl][kt][2] = *(const uint32_t*)(q0 + c + 8);
            qf[sl][kt][3] = *(const uint32_t*)(q1 + c + 8);
        }
    }

    float o[2][8][4];
#pragma unroll
    for (int sl = 0; sl < 2; sl++)
#pragma unroll
        for (int nt = 0; nt < 8; nt++)
#pragma unroll
            for (int c = 0; c < 4; c++) o[sl][nt][c] = 0.0f;
    float lf[2][4];
#pragma unroll
    for (int sl = 0; sl < 2; sl++)
#pragma unroll
        for (int c = 0; c < 4; c++) lf[sl][c] = 0.0f;

    const __half2 shift2 = __floats2half2_rn(SM_SHIFT, SM_SHIFT);
    const uint32_t ones = 0x3C003C00u;            // half2(1,1)
    const uint32_t ones_b[2] = {ones, ones};

    const int nIters = 2 * (qt + 1);

    auto load_tile = [&](int t, int st) {
        const __half* kb = K + ((size_t)(b * N_ + t * 64)) * DM + h * HD;
        const __half* vb = V + ((size_t)(b * N_ + t * 64)) * DM + h * HD;
#pragma unroll
        for (int j = 0; j < 8; j++) {
            int i = tid + 128 * j;
            int rem = i & 511;
            int row = rem >> 3, ch = rem & 7;
            int soff = row * 64 + ((ch ^ (row & 7)) << 3);
            if (i < 512) cp16(&Ks[st][soff], kb + (size_t)row * DM + ch * 8);
            else         cp16(&Vs[st][soff], vb + (size_t)row * DM + ch * 8);
        }
        cp_commit();
    };

    load_tile(0, 0);

    for (int t = 0; t < nIters; t++) {
        cp_wait0();
        __syncthreads();
        if (t + 1 < nIters) load_tile(t + 1, (t + 1) & 1);

        const __half* Kb = Ks[t & 1];
        const __half* Vb = Vs[t & 1];

        // ---- S = Q K^T ----
        float s[2][8][4];
#pragma unroll
        for (int sl = 0; sl < 2; sl++)
#pragma unroll
            for (int nt = 0; nt < 8; nt++)
#pragma unroll
                for (int c = 0; c < 4; c++) s[sl][nt][c] = 0.0f;

#pragma unroll
        for (int kt = 0; kt < 4; kt++) {
#pragma unroll
            for (int p = 0; p < 4; p++) {
                uint32_t t4[4];
                int krow = p * 16 + (q >> 1) * 8 + rr;
                int dch = kt * 2 + (q & 1);
                ldsm_x4(t4, &Kb[krow * 64 + ((dch ^ (krow & 7)) << 3)]);
                uint32_t b0v[2] = {t4[0], t4[1]};
                uint32_t b1v[2] = {t4[2], t4[3]};
                mma_f16(s[0][2 * p],     qf[0][kt], b0v);
                mma_f16(s[0][2 * p + 1], qf[0][kt], b1v);
                mma_f16(s[1][2 * p],     qf[1][kt], b0v);
                mma_f16(s[1][2 * p + 1], qf[1][kt], b1v);
            }
        }

        // ---- causal mask (diagonal-overlap tiles only) ----
        if ((t * 64 + 63) > rowbase) {
#pragma unroll
            for (int sl = 0; sl < 2; sl++)
#pragma unroll
                for (int nt = 0; nt < 8; nt++) {
                    int key = t * 64 + nt * 8 + 2 * tig;
                    if (key > rq[sl][0])     s[sl][nt][0] = NEG_BIG;
                    if (key + 1 > rq[sl][0]) s[sl][nt][1] = NEG_BIG;
                    if (key > rq[sl][1])     s[sl][nt][2] = NEG_BIG;
                    if (key + 1 > rq[sl][1]) s[sl][nt][3] = NEG_BIG;
                }
        }

        // ---- P = exp2(S - 4); O += P V; P-fragments summed over kt in f16 ----
        uint32_t paSum[2][4];
#pragma unroll
        for (int kt = 0; kt < 4; kt++) {
            uint32_t pa[2][4];
#pragma unroll
            for (int sl = 0; sl < 2; sl++) {
                __half2 h0v = __hsub2(__floats2half2_rn(s[sl][2 * kt][0],     s[sl][2 * kt][1]),     shift2);
                __half2 h1v = __hsub2(__floats2half2_rn(s[sl][2 * kt][2],     s[sl][2 * kt][3]),     shift2);
                __half2 h2v = __hsub2(__floats2half2_rn(s[sl][2 * kt + 1][0], s[sl][2 * kt + 1][1]), shift2);
                __half2 h3v = __hsub2(__floats2half2_rn(s[sl][2 * kt + 1][2], s[sl][2 * kt + 1][3]), shift2);
                pa[sl][0] = ex2_h2(*(uint32_t*)&h0v);
                pa[sl][1] = ex2_h2(*(uint32_t*)&h1v);
                pa[sl][2] = ex2_h2(*(uint32_t*)&h2v);
                pa[sl][3] = ex2_h2(*(uint32_t*)&h3v);
                if (kt == 0) {
                    paSum[sl][0] = pa[sl][0];
                    paSum[sl][1] = pa[sl][1];
                    paSum[sl][2] = pa[sl][2];
                    paSum[sl][3] = pa[sl][3];
                } else {
                    paSum[sl][0] = hadd2u(paSum[sl][0], pa[sl][0]);
                    paSum[sl][1] = hadd2u(paSum[sl][1], pa[sl][1]);
                    paSum[sl][2] = hadd2u(paSum[sl][2], pa[sl][2]);
                    paSum[sl][3] = hadd2u(paSum[sl][3], pa[sl][3]);
                }
            }
#pragma unroll
            for (int p = 0; p < 4; p++) {
                uint32_t t4[4];
                int krow = kt * 16 + (q & 1) * 8 + rr;
                int dch = 2 * p + (q >> 1);
                ldsm_x4_t(t4, &Vb[krow * 64 + ((dch ^ (krow & 7)) << 3)]);
                uint32_t b0v[2] = {t4[0], t4[1]};
                uint32_t b1v[2] = {t4[2], t4[3]};
                mma_f16(o[0][2 * p],     pa[0], b0v);
                mma_f16(o[0][2 * p + 1], pa[0], b1v);
                mma_f16(o[1][2 * p],     pa[1], b0v);
                mma_f16(o[1][2 * p + 1], pa[1], b1v);
            }
        }
        // one deferred ones-mma per slab: l += (Σ_kt P_kt) @ ones
        mma_f16(lf[0], paSum[0], ones_b);
        mma_f16(lf[1], paSum[1], ones_b);
    }

    // ---- epilogue: normalize by l, store fp16 ----
#pragma unroll
    for (int sl = 0; sl < 2; sl++) {
        float inv0 = 1.0f / lf[sl][0], inv1 = 1.0f / lf[sl][2];
        __half* c0 = Ctx + ((size_t)(b * N_ + rq[sl][0])) * DM + h * HD;
        __half* c1 = Ctx + ((size_t)(b * N_ + rq[sl][1])) * DM + h * HD;
#pragma unroll
        for (int nt = 0; nt < 8; nt++) {
            int col = nt * 8 + 2 * tig;
            __half2 v0 = __floats2half2_rn(o[sl][nt][0] * inv0, o[sl][nt][1] * inv0);
            __half2 v1 = __floats2half2_rn(o[sl][nt][2] * inv1, o[sl][nt][3] * inv1);
            *(__half2*)(c0 + col) = v0;
            *(__half2*)(c1 + col) = v1;
        }
    }
}

// ---------------------------------------------------------------------------
// Launch: batch-split two-stream pipeline; parallel cast prefix folded into
// the SAME two side streams (no extra streams -> no upload alloc).
// ---------------------------------------------------------------------------
#define GEMM_SMEM (2 * (128 * 64 + 64 * 128) * (int)sizeof(__half))  // 64 KB

extern "C" void kernel_launch(void* const* d_in, const int* in_sizes, int n_in,
                              void* d_out, int out_size)
{
    const float* x  = (const float*)d_in[0];
    const float* Wq = (const float*)d_in[1];
    const float* Wk = (const float*)d_in[2];
    const float* Wv = (const float*)d_in[3];
    const float* Wo = (const float*)d_in[4];
    float* out = (float*)d_out;

    __half *Xh, *Wqh, *Wkh, *Wvh, *Woh, *Qh, *Kh, *Vh, *Ch;
    cudaGetSymbolAddress((void**)&Xh, g_Xh);
    cudaGetSymbolAddress((void**)&Wqh, g_Wqh);
    cudaGetSymbolAddress((void**)&Wkh, g_Wkh);
    cudaGetSymbolAddress((void**)&Wvh, g_Wvh);
    cudaGetSymbolAddress((void**)&Woh, g_Woh);
    cudaGetSymbolAddress((void**)&Qh, g_Qh);
    cudaGetSymbolAddress((void**)&Kh, g_Kh);
    cudaGetSymbolAddress((void**)&Vh, g_Vh);
    cudaGetSymbolAddress((void**)&Ch, g_Ch);

    static cudaStream_t s2 = nullptr, s3 = nullptr;
    static cudaEvent_t evRoot = nullptr, evWqk = nullptr, evWv = nullptr;
    static cudaEvent_t evWo = nullptr, evJ = nullptr;
    static bool init_done = false;
    if (!init_done) {
        cudaFuncSetAttribute(gemm_f16<true>,  cudaFuncAttributeMaxDynamicSharedMemorySize, GEMM_SMEM);
        cudaFuncSetAttribute(gemm_f16<false>, cudaFuncAttributeMaxDynamicSharedMemorySize, GEMM_SMEM);
        cudaStreamCreateWithFlags(&s2, cudaStreamNonBlocking);
        cudaStreamCreateWithFlags(&s3, cudaStreamNonBlocking);
        cudaEventCreateWithFlags(&evRoot, cudaEventDisableTiming);
        cudaEventCreateWithFlags(&evWqk, cudaEventDisableTiming);
        cudaEventCreateWithFlags(&evWv, cudaEventDisableTiming);
        cudaEventCreateWithFlags(&evWo, cudaEventDisableTiming);
        cudaEventCreateWithFlags(&evJ, cudaEventDisableTiming);
        init_done = true;
    }

    const int n4x = MTOT * DM / 4, n4w = DM * DM / 4;
    const int n4xh = n4x / 2;   // x half (one batch)

    // ---- capture-legal fork of the two side streams from the origin ----
    cudaEventRecord(evRoot, 0);
    cudaStreamWaitEvent(s2, evRoot, 0);
    cudaStreamWaitEvent(s3, evRoot, 0);

    // ---- parallel cast prefix (2 side streams only) ----
    cast_half<<<(n4w + 255) / 256, 256, 0, s3>>>((const float4*)Wq, (uint2*)Wqh, n4w);
    cast_half<<<(n4w + 255) / 256, 256, 0, s3>>>((const float4*)Wk, (uint2*)Wkh, n4w);
    cudaEventRecord(evWqk, s3);
    cast_half<<<(n4w + 255) / 256, 256, 0, s3>>>((const float4*)Wo, (uint2*)Woh, n4w);
    cudaEventRecord(evWo, s3);
    cast_half<<<(n4w + 255) / 256, 256, 0, s2>>>((const float4*)Wv, (uint2*)Wvh, n4w);
    cudaEventRecord(evWv, s2);
    cast_half<<<(n4xh + 255) / 256, 256, 0, s2>>>((const float4*)x + n4xh,
                                                  (uint2*)Xh + n4xh, n4xh);
    cast_half<<<(n4xh + 255) / 256, 256>>>((const float4*)x, (uint2*)Xh, n4xh);

    cudaStreamWaitEvent(0, evWqk, 0);
    cudaStreamWaitEvent(0, evWv, 0);
    cudaStreamWaitEvent(s2, evWqk, 0);

    const float qalpha = 0.125f * 1.4426950408889634f;
    GArgs qkv;
    qkv.B[0] = Wqh; qkv.B[1] = Wkh; qkv.B[2] = Wvh;
    qkv.C[0] = Qh;  qkv.C[1] = Kh;  qkv.C[2] = Vh;
    qkv.alpha[0] = qalpha; qkv.alpha[1] = 1.0f; qkv.alpha[2] = 1.0f;

    GArgs og;
    og.B[0] = Woh; og.C[0] = out; og.alpha[0] = 1.0f;
    og.B[1] = Woh; og.C[1] = out; og.alpha[1] = 1.0f;
    og.B[2] = Woh; og.C[2] = out; og.alpha[2] = 1.0f;

    // ---- stream 0: full chain for batch 0 (M-tiles 0..15) ----
    gemm_f16<true><<<dim3(8, 16, 3), 256, GEMM_SMEM>>>(Xh, qkv, MTOT, DM, DM, 0);
    attn_f16<<<dim3(N_ / 128, H_, 1), 128>>>(Qh, Kh, Vh, Ch, 0);
    cudaStreamWaitEvent(0, evWo, 0);
    gemm_f16<false><<<dim3(8, 16, 1), 256, GEMM_SMEM>>>(Ch, og, MTOT, DM, DM, 0);

    // ---- stream s2: full chain for batch 1 (M-tiles 16..31) ----
    gemm_f16<true><<<dim3(8, 16, 3), 256, GEMM_SMEM, s2>>>(Xh, qkv, MTOT, DM, DM, 16);
    attn_f16<<<dim3(N_ / 128, H_, 1), 128, 0, s2>>>(Qh, Kh, Vh, Ch, 1);
    cudaStreamWaitEvent(s2, evWo, 0);
    gemm_f16<false><<<dim3(8, 16, 1), 256, GEMM_SMEM, s2>>>(Ch, og, MTOT, DM, DM, 16);

    // ---- join: origin stream waits for s2's chain ----
    cudaEventRecord(evJ, s2);
    cudaStreamWaitEvent(0, evJ, 0);
}